// round 12
// baseline (speedup 1.0000x reference)
#include <cuda_runtime.h>
#include <cuda_fp16.h>
#include <cstdint>

// ---------------- smem layout (bytes) ----------------
#define B_SPLIT  25600          // 160 k-pairs x 160B (word (e>>1)*160 + j*4 + (e&1)*2)
#define SB_B     0
#define SB_THR   25600          // 32 floats: 0.2*||a_j||
#define SB_WAON  25728          // 32 floats: w_j/||a_j||
#define SB_AN    25856          // 32 floats: ||a_j||
#define SMEM_TOT 25984

__device__ float g_ctable[50048];

__device__ __forceinline__ uint32_t h2u(__half2 h) {
    union { __half2 h; uint32_t u; } cv; cv.h = h; return cv.u;
}

__device__ __forceinline__ void mma16816(float* d, const uint32_t* a, const uint32_t* b) {
    asm volatile(
        "mma.sync.aligned.m16n8k16.row.col.f32.f16.f16.f32 "
        "{%0,%1,%2,%3}, {%4,%5,%6,%7}, {%8,%9}, {%0,%1,%2,%3};"
        : "+f"(d[0]), "+f"(d[1]), "+f"(d[2]), "+f"(d[3])
        : "r"(a[0]), "r"(a[1]), "r"(a[2]), "r"(a[3]), "r"(b[0]), "r"(b[1]));
}

__device__ __forceinline__ float2 ldw2(const float* p, bool ok) {
    return ok ? __ldg((const float2*)p) : make_float2(0.f, 0.f);
}

// single code instance: exact fp32 dot over 300 elements (rare path)
__device__ __noinline__ float exact_dot300(const float* __restrict__ wr,
                                           const float* __restrict__ ar) {
    float s0 = 0.f, s1 = 0.f, s2 = 0.f, s3 = 0.f;
#pragma unroll 1
    for (int e = 0; e < 300; e += 4) {
        s0 = fmaf(wr[e],     ar[e],     s0);
        s1 = fmaf(wr[e + 1], ar[e + 1], s1);
        s2 = fmaf(wr[e + 2], ar[e + 2], s2);
        s3 = fmaf(wr[e + 3], ar[e + 3], s3);
    }
    return (s0 + s1) + (s2 + s3);
}

// ---------------- vocab GEMM: 1-product fp16 HMMA + certified selective recompute ----------------
__global__ __launch_bounds__(256, 3) void vocab_mma(const float* __restrict__ w_emb,
                                                    const float* __restrict__ a_emb,
                                                    const float* __restrict__ a_wt,
                                                    int V) {
    extern __shared__ char smem[];
    const int tid = threadIdx.x, lane = tid & 31, wid = tid >> 5;
    const int g = lane >> 2, t = lane & 3;          // mma fragment mapping

    for (int i = tid; i < B_SPLIT / 16; i += 256)
        *(uint4*)(smem + SB_B + i * 16) = make_uint4(0, 0, 0, 0);
    if (tid < 32) {
        *(float*)(smem + SB_THR  + tid * 4) = 3.0e38f;
        *(float*)(smem + SB_WAON + tid * 4) = 0.f;
        *(float*)(smem + SB_AN   + tid * 4) = 0.f;
    }
    __syncthreads();

    // fill B (aspects): element (k=e, n=j) -> word (e>>1)*160 + j*4 (+2 if e odd)
    for (int idx = tid; idx < 30 * 300; idx += 256) {
        int j = idx / 300, e = idx - j * 300;
        *(__half*)(smem + SB_B + (uint32_t)((e >> 1) * 160 + j * 4 + (e & 1) * 2)) =
            __float2half_rn(a_emb[idx]);
    }

    // aspect norms -> thr/waon/an
    {
        int j = tid >> 3, e8 = tid & 7;
        int jj = (j < 30) ? j : 0;
        float s = 0.f;
        for (int e = e8; e < 300; e += 8) { float v = a_emb[jj * 300 + e]; s = fmaf(v, v, s); }
        s += __shfl_xor_sync(0xffffffffu, s, 1);
        s += __shfl_xor_sync(0xffffffffu, s, 2);
        s += __shfl_xor_sync(0xffffffffu, s, 4);
        if (j < 30 && e8 == 0) {
            float an = fmaxf(sqrtf(s), 1e-8f);
            *(float*)(smem + SB_THR  + j * 4) = 0.2f * an;
            *(float*)(smem + SB_WAON + j * 4) = a_wt[j] / an;
            *(float*)(smem + SB_AN   + j * 4) = an;
        }
    }
    __syncthreads();

    const int r0 = wid * 16 + g, r1 = r0 + 8;
    const int gr0 = blockIdx.x * 128 + r0, gr1 = blockIdx.x * 128 + r1;
    const bool rok0 = gr0 < V, rok1 = gr1 < V;
    const float* p0 = w_emb + (size_t)(rok0 ? gr0 : 0) * 300 + 2 * t;
    const float* p1 = w_emb + (size_t)(rok1 ? gr1 : 0) * 300 + 2 * t;

    float d[4][4];
#pragma unroll
    for (int nt = 0; nt < 4; nt++)
#pragma unroll
        for (int i = 0; i < 4; i++) d[nt][i] = 0.f;
    float nrm0 = 0.f, nrm1 = 0.f;

    float2 cur0 = ldw2(p0,      rok0);
    float2 cur1 = ldw2(p0 + 8,  rok0);
    float2 cur2 = ldw2(p1,      rok1);
    float2 cur3 = ldw2(p1 + 8,  rok1);

#pragma unroll 1
    for (int k16 = 0; k16 < 19; k16++) {
        float2 nx0 = make_float2(0.f, 0.f), nx1 = nx0, nx2 = nx0, nx3 = nx0;
        if (k16 < 18) {
            const float* q0 = p0 + (k16 + 1) * 16;
            const float* q1 = p1 + (k16 + 1) * 16;
            bool hok = (k16 + 1 < 18) | (t < 2);
            nx0 = ldw2(q0,     rok0);
            nx1 = ldw2(q0 + 8, rok0 & hok);
            nx2 = ldw2(q1,     rok1);
            nx3 = ldw2(q1 + 8, rok1 & hok);
        }

        // single-limb fp16 A fragments
        uint32_t af[4];
        af[0] = h2u(__float22half2_rn(cur0));
        af[1] = h2u(__float22half2_rn(cur2));
        af[2] = h2u(__float22half2_rn(cur1));
        af[3] = h2u(__float22half2_rn(cur3));

        nrm0 = fmaf(cur0.x, cur0.x, nrm0); nrm0 = fmaf(cur0.y, cur0.y, nrm0);
        nrm0 = fmaf(cur1.x, cur1.x, nrm0); nrm0 = fmaf(cur1.y, cur1.y, nrm0);
        nrm1 = fmaf(cur2.x, cur2.x, nrm1); nrm1 = fmaf(cur2.y, cur2.y, nrm1);
        nrm1 = fmaf(cur3.x, cur3.x, nrm1); nrm1 = fmaf(cur3.y, cur3.y, nrm1);

        // B fragments (conflict-free LDS.32)
        uint32_t sbase = (uint32_t)((k16 * 8 + t) * 160 + g * 4);
#pragma unroll
        for (int nt = 0; nt < 4; nt++) {
            uint32_t bf[2];
            bf[0] = *(const uint32_t*)(smem + SB_B + sbase + nt * 32);
            bf[1] = *(const uint32_t*)(smem + SB_B + sbase + nt * 32 + 640);
            mma16816(d[nt], af, bf);
        }

        cur0 = nx0; cur1 = nx1; cur2 = nx2; cur3 = nx3;
    }

    nrm0 += __shfl_xor_sync(0xffffffffu, nrm0, 1);
    nrm0 += __shfl_xor_sync(0xffffffffu, nrm0, 2);
    nrm1 += __shfl_xor_sync(0xffffffffu, nrm1, 1);
    nrm1 += __shfl_xor_sync(0xffffffffu, nrm1, 2);
    float nxr0 = fmaxf(sqrtf(nrm0), 1e-8f);
    float nxr1 = fmaxf(sqrtf(nrm1), 1e-8f);

    // epilogue: certified threshold + max over aspects.
    // Any dot above (tc - band) is recomputed exactly in fp32, so every passer
    // and every near-threshold case is exact. band >= 2^-10*||w||*||a|| worst case.
    const float* thr  = (const float*)(smem + SB_THR);
    const float* waon = (const float*)(smem + SB_WAON);
    const float* anv  = (const float*)(smem + SB_AN);
    float best0 = 0.f, best1 = 0.f;

#pragma unroll
    for (int nt = 0; nt < 4; nt++) {
#pragma unroll
        for (int i = 0; i < 4; i++) {
            int j  = nt * 8 + 2 * t + (i & 1);
            int gr = (i < 2) ? gr0 : gr1;
            bool rk = (i < 2) ? rok0 : rok1;
            float nx = (i < 2) ? nxr0 : nxr1;
            float dot = d[nt][i];
            float tc   = thr[j] * nx;
            float band = 1.0e-3f * anv[j] * nx + 1e-5f;
            if (rk && dot > tc - band) {
                dot = exact_dot300(w_emb + (size_t)gr * 300, a_emb + (size_t)j * 300);
                if (dot > tc) {
                    float v = dot * waon[j];
                    if (i < 2) best0 = fmaxf(best0, v);
                    else       best1 = fmaxf(best1, v);
                }
            }
        }
    }
    best0 = fmaxf(best0, __shfl_xor_sync(0xffffffffu, best0, 1));
    best0 = fmaxf(best0, __shfl_xor_sync(0xffffffffu, best0, 2));
    best1 = fmaxf(best1, __shfl_xor_sync(0xffffffffu, best1, 1));
    best1 = fmaxf(best1, __shfl_xor_sync(0xffffffffu, best1, 2));
    if (t == 0) {
        if (rok0) g_ctable[gr0] = best0 / nxr0;
        if (rok1) g_ctable[gr1] = best1 / nxr1;
    }
}

// ---------------- row kernel (round-7 block version) ----------------
__global__ __launch_bounds__(256) void row_kernel(const int* __restrict__ tokens,
                                                  const float* __restrict__ w_emb,
                                                  float* __restrict__ enc,
                                                  float* __restrict__ attn,
                                                  float* __restrict__ cscore,
                                                  int L, int E) {
    int b = blockIdx.x;
    int l = threadIdx.x;
    int lane = l & 31, wid = l >> 5;

    __shared__ float red_m[8], red_s[8];
    __shared__ int   red_n[8];
    __shared__ float bc_max, bc_cs, bc_den;
    __shared__ int   s_woff[8], s_n;
    __shared__ int   s_tok[256];
    __shared__ float s_w[256];

    int tok   = tokens[(size_t)b * L + l];
    float c   = g_ctable[tok];
    float score = (c > 0.f) ? c : -1e9f;
    int   cnt = (tok != 0) ? 1 : 0;

    float m = score, sc = c; int cn = cnt;
#pragma unroll
    for (int o = 16; o; o >>= 1) {
        m  = fmaxf(m, __shfl_xor_sync(0xffffffffu, m, o));
        sc += __shfl_xor_sync(0xffffffffu, sc, o);
        cn += __shfl_xor_sync(0xffffffffu, cn, o);
    }
    if (lane == 0) { red_m[wid] = m; red_s[wid] = sc; red_n[wid] = cn; }
    __syncthreads();
    if (l == 0) {
        float M = red_m[0], S = red_s[0]; int N = red_n[0];
#pragma unroll
        for (int i = 1; i < 8; i++) { M = fmaxf(M, red_m[i]); S += red_s[i]; N += red_n[i]; }
        bc_max = M;
        bc_cs  = S / ((float)N + 1e-5f);
    }
    __syncthreads();

    float M  = bc_max;
    float cs = bc_cs;
    float e  = expf(score - M);

    float se = e;
#pragma unroll
    for (int o = 16; o; o >>= 1) se += __shfl_xor_sync(0xffffffffu, se, o);
    if (lane == 0) red_s[wid] = se;
    __syncthreads();
    if (l == 0) {
        float D = red_s[0];
#pragma unroll
        for (int i = 1; i < 8; i++) D += red_s[i];
        bc_den = D;
    }
    __syncthreads();

    float a = e / bc_den;
    attn[(size_t)b * L + l] = a;
    if (l == 0) cscore[b] = cs;

    bool gate = cs > 1e-4f;
    if (gate) {
        bool act = (e > 0.f);
        unsigned mask = __ballot_sync(0xffffffffu, act);
        if (lane == 0) s_woff[wid] = __popc(mask);
        __syncthreads();
        if (l == 0) {
            int o = 0;
#pragma unroll
            for (int i = 0; i < 8; i++) { int tt = s_woff[i]; s_woff[i] = o; o += tt; }
            s_n = o;
        }
        __syncthreads();
        if (act) {
            int pos = s_woff[wid] + __popc(mask & ((1u << lane) - 1u));
            s_tok[pos] = tok;
            s_w[pos]   = a;
        }
        __syncthreads();
        int n = s_n;
        for (int j = l; j < E; j += 256) {
            float z = 0.f;
            for (int i = 0; i < n; i++)
                z = fmaf(s_w[i], w_emb[(size_t)s_tok[i] * E + j], z);
            enc[(size_t)b * E + j] = z;
        }
    } else {
        for (int j = l; j < E; j += 256)
            enc[(size_t)b * E + j] = 0.f;
    }
}

// ---------------- launch ----------------
extern "C" void kernel_launch(void* const* d_in, const int* in_sizes, int n_in,
                              void* d_out, int out_size) {
    const int*   inputs = (const int*)d_in[0];     // [B, L]
    const float* w_emb  = (const float*)d_in[1];   // [V, E]
    const float* a_emb  = (const float*)d_in[2];   // [A, E]
    const float* a_w    = (const float*)d_in[3];   // [A]

    int BL = in_sizes[0];
    int A  = in_sizes[3];
    int E  = in_sizes[2] / A;        // 300
    int V  = in_sizes[1] / E;        // 50000
    int L  = 256;
    int B  = BL / L;                 // 1024

    vocab_mma<<<(V + 127) / 128, 256, SMEM_TOT>>>(w_emb, a_emb, a_w, V);

    float* out    = (float*)d_out;
    float* enc    = out;                                   // [B, E]
    float* attn   = out + (size_t)B * E;                   // [B, L]
    float* cscore = out + (size_t)B * E + (size_t)B * L;   // [B]
    row_kernel<<<B, 256>>>(inputs, w_emb, enc, attn, cscore, L, E);
}

// round 13
// speedup vs baseline: 1.6737x; 1.6737x over previous
#include <cuda_runtime.h>
#include <cuda_fp16.h>
#include <cstdint>

// ---------------- smem layout (bytes) ----------------
#define B_SPLIT  25600          // 160 k-pairs x 160B
#define SB_B     0
#define SB_THR   51200          // 32 floats
#define SB_WAON  51328          // 32 floats
#define SMEM_TOT 51456

__device__ float g_ctable[50048];

__device__ __forceinline__ uint32_t h2u(__half2 h) {
    union { __half2 h; uint32_t u; } cv; cv.h = h; return cv.u;
}
__device__ __forceinline__ float2 u2f2(uint32_t u) {
    union { uint32_t u; __half2 h; } cv; cv.u = u;
    return __half22float2(cv.h);
}

// 2-limb fp16 split of a pair -> two fragment words
__device__ __forceinline__ void split2pack(float x, float y, uint32_t& s0, uint32_t& s1) {
    __half2 h0 = __float22half2_rn(make_float2(x, y));
    float2 f0 = __half22float2(h0);
    __half2 h1 = __float22half2_rn(make_float2(x - f0.x, y - f0.y));
    s0 = h2u(h0);
    s1 = h2u(h1);
}

__device__ __forceinline__ void mma16816(float* d, const uint32_t* a, const uint32_t* b) {
    asm volatile(
        "mma.sync.aligned.m16n8k16.row.col.f32.f16.f16.f32 "
        "{%0,%1,%2,%3}, {%4,%5,%6,%7}, {%8,%9}, {%0,%1,%2,%3};"
        : "+f"(d[0]), "+f"(d[1]), "+f"(d[2]), "+f"(d[3])
        : "r"(a[0]), "r"(a[1]), "r"(a[2]), "r"(a[3]), "r"(b[0]), "r"(b[1]));
}
__device__ __forceinline__ void mma16816h(uint32_t* c, const uint32_t* a, const uint32_t* b) {
    asm volatile(
        "mma.sync.aligned.m16n8k16.row.col.f16.f16.f16.f16 "
        "{%0,%1}, {%2,%3,%4,%5}, {%6,%7}, {%0,%1};"
        : "+r"(c[0]), "+r"(c[1])
        : "r"(a[0]), "r"(a[1]), "r"(a[2]), "r"(a[3]), "r"(b[0]), "r"(b[1]));
}

__device__ __forceinline__ float4 ldw4(const float4* p, bool ok) {
    return ok ? __ldg(p) : make_float4(0.f, 0.f, 0.f, 0.f);
}

// ---------------- vocab GEMM (R10 numerics + permuted float4 fragment loads) ----------------
__global__ __launch_bounds__(256, 3) void vocab_mma(const float* __restrict__ w_emb,
                                                    const float* __restrict__ a_emb,
                                                    const float* __restrict__ a_wt,
                                                    int V) {
    extern __shared__ char smem[];
    const int tid = threadIdx.x, lane = tid & 31, wid = tid >> 5;
    const int g = lane >> 2, t = lane & 3;          // mma fragment mapping

    for (int i = tid; i < 2 * B_SPLIT / 16; i += 256)
        *(uint4*)(smem + SB_B + i * 16) = make_uint4(0, 0, 0, 0);
    if (tid < 32) {
        *(float*)(smem + SB_THR + tid * 4) = 3.0e38f;
        *(float*)(smem + SB_WAON + tid * 4) = 0.f;
    }
    __syncthreads();

    // fill B (aspects) with the k-permutation matching float4 A loads:
    // element e: k16=e>>4, r=e&15, tt=r>>2, s=r&3
    // pair index = k16*8 + (s>>1)*4 + tt, half = s&1
    for (int idx = tid; idx < 30 * 300; idx += 256) {
        int j = idx / 300, e = idx - j * 300;
        float f = a_emb[idx];
        __half h0 = __float2half_rn(f);
        __half h1 = __float2half_rn(f - __half2float(h0));
        int k16 = e >> 4, r = e & 15;
        int tt = r >> 2, s = r & 3;
        uint32_t base = (uint32_t)((k16 * 8 + (s >> 1) * 4 + tt) * 160 + j * 4 + (s & 1) * 2);
        *(__half*)(smem + SB_B + base)           = h0;
        *(__half*)(smem + SB_B + B_SPLIT + base) = h1;
    }

    // aspect norms -> thr/waon
    {
        int j = tid >> 3, e8 = tid & 7;
        int jj = (j < 30) ? j : 0;
        float s = 0.f;
        for (int e = e8; e < 300; e += 8) { float v = a_emb[jj * 300 + e]; s = fmaf(v, v, s); }
        s += __shfl_xor_sync(0xffffffffu, s, 1);
        s += __shfl_xor_sync(0xffffffffu, s, 2);
        s += __shfl_xor_sync(0xffffffffu, s, 4);
        if (j < 30 && e8 == 0) {
            float an = fmaxf(sqrtf(s), 1e-8f);
            *(float*)(smem + SB_THR + j * 4)  = 0.2f * an;
            *(float*)(smem + SB_WAON + j * 4) = a_wt[j] / an;
        }
    }
    __syncthreads();

    const int r0 = wid * 16 + g, r1 = r0 + 8;
    const int gr0 = blockIdx.x * 128 + r0, gr1 = blockIdx.x * 128 + r1;
    const bool rok0 = gr0 < V, rok1 = gr1 < V;
    // one float4 per row per k16: element 16*k16 + 4t  -> float4 index 4*k16 + t
    const float4* p0 = (const float4*)(w_emb + (size_t)(rok0 ? gr0 : 0) * 300) + t;
    const float4* p1 = (const float4*)(w_emb + (size_t)(rok1 ? gr1 : 0) * 300) + t;

    float d[4][4];
    uint32_t hc[4][2];
#pragma unroll
    for (int nt = 0; nt < 4; nt++) {
#pragma unroll
        for (int i = 0; i < 4; i++) d[nt][i] = 0.f;
        hc[nt][0] = 0u; hc[nt][1] = 0u;
    }
    float nrm0 = 0.f, nrm1 = 0.f;

    // prefetch k16 = 0  (t=3 covers e 12..15 -> in range)
    float4 w0 = ldw4(p0, rok0);
    float4 w1 = ldw4(p1, rok1);

#pragma unroll 1
    for (int k16 = 0; k16 < 19; k16++) {
        // prefetch next step: last step's t=3 covers e 300..303 -> OOB, zero it
        float4 q0 = make_float4(0.f, 0.f, 0.f, 0.f), q1 = q0;
        if (k16 < 18) {
            bool ok = (k16 + 1 < 18) | (t < 3);
            q0 = ldw4(p0 + (k16 + 1) * 4, rok0 & ok);
            q1 = ldw4(p1 + (k16 + 1) * 4, rok1 & ok);
        }

        // convert fragments in-register (word0 = x,y ; word1 = z,w)
        uint32_t af[2][4];
        split2pack(w0.x, w0.y, af[0][0], af[1][0]);
        split2pack(w1.x, w1.y, af[0][1], af[1][1]);
        split2pack(w0.z, w0.w, af[0][2], af[1][2]);
        split2pack(w1.z, w1.w, af[0][3], af[1][3]);
        nrm0 = fmaf(w0.x, w0.x, nrm0); nrm0 = fmaf(w0.y, w0.y, nrm0);
        nrm0 = fmaf(w0.z, w0.z, nrm0); nrm0 = fmaf(w0.w, w0.w, nrm0);
        nrm1 = fmaf(w1.x, w1.x, nrm1); nrm1 = fmaf(w1.y, w1.y, nrm1);
        nrm1 = fmaf(w1.z, w1.z, nrm1); nrm1 = fmaf(w1.w, w1.w, nrm1);

        // B fragments (same addresses as before; fill was permuted to match)
        uint32_t bf[2][4][2];
        uint32_t sbase = (uint32_t)((k16 * 8 + t) * 160 + g * 4);
#pragma unroll
        for (int s = 0; s < 2; s++) {
            uint32_t sb = SB_B + (uint32_t)s * B_SPLIT + sbase;
#pragma unroll
            for (int nt = 0; nt < 4; nt++) {
                bf[s][nt][0] = *(const uint32_t*)(smem + sb + nt * 32);
                bf[s][nt][1] = *(const uint32_t*)(smem + sb + nt * 32 + 640);
            }
        }

#pragma unroll
        for (int nt = 0; nt < 4; nt++) {
            mma16816(d[nt],   af[0], bf[0][nt]);   // w0*a0 (fp32 acc)
            mma16816h(hc[nt], af[0], bf[1][nt]);   // w0*a1 (fp16 acc)
            mma16816h(hc[nt], af[1], bf[0][nt]);   // w1*a0 (fp16 acc)
        }

        w0 = q0; w1 = q1;
    }

    // fold fp16 corrections into fp32 accumulators
#pragma unroll
    for (int nt = 0; nt < 4; nt++) {
        float2 clo = u2f2(hc[nt][0]);
        float2 chi = u2f2(hc[nt][1]);
        d[nt][0] += clo.x; d[nt][1] += clo.y;
        d[nt][2] += chi.x; d[nt][3] += chi.y;
    }

    nrm0 += __shfl_xor_sync(0xffffffffu, nrm0, 1);
    nrm0 += __shfl_xor_sync(0xffffffffu, nrm0, 2);
    nrm1 += __shfl_xor_sync(0xffffffffu, nrm1, 1);
    nrm1 += __shfl_xor_sync(0xffffffffu, nrm1, 2);
    float nx0 = fmaxf(sqrtf(nrm0), 1e-8f);
    float nx1 = fmaxf(sqrtf(nrm1), 1e-8f);

    float b0 = 0.f, b1 = 0.f;
#pragma unroll
    for (int nt = 0; nt < 4; nt++) {
        int j0 = nt * 8 + 2 * t, j1 = j0 + 1;
        float th0 = *(const float*)(smem + SB_THR + j0 * 4);
        float th1 = *(const float*)(smem + SB_THR + j1 * 4);
        float wa0 = *(const float*)(smem + SB_WAON + j0 * 4);
        float wa1 = *(const float*)(smem + SB_WAON + j1 * 4);
        if (d[nt][0] > th0 * nx0) b0 = fmaxf(b0, d[nt][0] * wa0);
        if (d[nt][1] > th1 * nx0) b0 = fmaxf(b0, d[nt][1] * wa1);
        if (d[nt][2] > th0 * nx1) b1 = fmaxf(b1, d[nt][2] * wa0);
        if (d[nt][3] > th1 * nx1) b1 = fmaxf(b1, d[nt][3] * wa1);
    }
    b0 = fmaxf(b0, __shfl_xor_sync(0xffffffffu, b0, 1));
    b0 = fmaxf(b0, __shfl_xor_sync(0xffffffffu, b0, 2));
    b1 = fmaxf(b1, __shfl_xor_sync(0xffffffffu, b1, 1));
    b1 = fmaxf(b1, __shfl_xor_sync(0xffffffffu, b1, 2));
    if (t == 0) {
        if (rok0) g_ctable[gr0] = b0 / nx0;
        if (rok1) g_ctable[gr1] = b1 / nx1;
    }
}

// ---------------- row kernel ----------------
__global__ __launch_bounds__(256) void row_kernel(const int* __restrict__ tokens,
                                                  const float* __restrict__ w_emb,
                                                  float* __restrict__ enc,
                                                  float* __restrict__ attn,
                                                  float* __restrict__ cscore,
                                                  int L, int E) {
    int b = blockIdx.x;
    int l = threadIdx.x;
    int lane = l & 31, wid = l >> 5;

    __shared__ float red_m[8], red_s[8];
    __shared__ int   red_n[8];
    __shared__ float bc_max, bc_cs, bc_den;
    __shared__ int   s_woff[8], s_n;
    __shared__ int   s_tok[256];
    __shared__ float s_w[256];

    int tok   = tokens[(size_t)b * L + l];
    float c   = g_ctable[tok];
    float score = (c > 0.f) ? c : -1e9f;
    int   cnt = (tok != 0) ? 1 : 0;

    float m = score, sc = c; int cn = cnt;
#pragma unroll
    for (int o = 16; o; o >>= 1) {
        m  = fmaxf(m, __shfl_xor_sync(0xffffffffu, m, o));
        sc += __shfl_xor_sync(0xffffffffu, sc, o);
        cn += __shfl_xor_sync(0xffffffffu, cn, o);
    }
    if (lane == 0) { red_m[wid] = m; red_s[wid] = sc; red_n[wid] = cn; }
    __syncthreads();
    if (l == 0) {
        float M = red_m[0], S = red_s[0]; int N = red_n[0];
#pragma unroll
        for (int i = 1; i < 8; i++) { M = fmaxf(M, red_m[i]); S += red_s[i]; N += red_n[i]; }
        bc_max = M;
        bc_cs  = S / ((float)N + 1e-5f);
    }
    __syncthreads();

    float M  = bc_max;
    float cs = bc_cs;
    float e  = expf(score - M);

    float se = e;
#pragma unroll
    for (int o = 16; o; o >>= 1) se += __shfl_xor_sync(0xffffffffu, se, o);
    if (lane == 0) red_s[wid] = se;
    __syncthreads();
    if (l == 0) {
        float D = red_s[0];
#pragma unroll
        for (int i = 1; i < 8; i++) D += red_s[i];
        bc_den = D;
    }
    __syncthreads();

    float a = e / bc_den;
    attn[(size_t)b * L + l] = a;
    if (l == 0) cscore[b] = cs;

    bool gate = cs > 1e-4f;
    if (gate) {
        bool act = (e > 0.f);
        unsigned mask = __ballot_sync(0xffffffffu, act);
        if (lane == 0) s_woff[wid] = __popc(mask);
        __syncthreads();
        if (l == 0) {
            int o = 0;
#pragma unroll
            for (int i = 0; i < 8; i++) { int tt = s_woff[i]; s_woff[i] = o; o += tt; }
            s_n = o;
        }
        __syncthreads();
        if (act) {
            int pos = s_woff[wid] + __popc(mask & ((1u << lane) - 1u));
            s_tok[pos] = tok;
            s_w[pos]   = a;
        }
        __syncthreads();
        int n = s_n;
        for (int j = l; j < E; j += 256) {
            float z = 0.f;
            for (int i = 0; i < n; i++)
                z = fmaf(s_w[i], w_emb[(size_t)s_tok[i] * E + j], z);
            enc[(size_t)b * E + j] = z;
        }
    } else {
        for (int j = l; j < E; j += 256)
            enc[(size_t)b * E + j] = 0.f;
    }
}

// ---------------- launch ----------------
extern "C" void kernel_launch(void* const* d_in, const int* in_sizes, int n_in,
                              void* d_out, int out_size) {
    const int*   inputs = (const int*)d_in[0];     // [B, L]
    const float* w_emb  = (const float*)d_in[1];   // [V, E]
    const float* a_emb  = (const float*)d_in[2];   // [A, E]
    const float* a_w    = (const float*)d_in[3];   // [A]

    int BL = in_sizes[0];
    int A  = in_sizes[3];
    int E  = in_sizes[2] / A;        // 300
    int V  = in_sizes[1] / E;        // 50000
    int L  = 256;
    int B  = BL / L;                 // 1024

    static bool attr_set = false;
    if (!attr_set) {
        cudaFuncSetAttribute(vocab_mma, cudaFuncAttributeMaxDynamicSharedMemorySize, SMEM_TOT);
        attr_set = true;
    }

    vocab_mma<<<(V + 127) / 128, 256, SMEM_TOT>>>(w_emb, a_emb, a_w, V);

    float* out    = (float*)d_out;
    float* enc    = out;                                   // [B, E]
    float* attn   = out + (size_t)B * E;                   // [B, L]
    float* cscore = out + (size_t)B * E + (size_t)B * L;   // [B]
    row_kernel<<<B, 256>>>(inputs, w_emb, enc, attn, cscore, L, E);
}